// round 6
// baseline (speedup 1.0000x reference)
#include <cuda_runtime.h>
#include <cuda_bf16.h>
#include <math.h>
#include <stdint.h>
#include <stddef.h>

#define T_DIM 2048
#define D_DIM 2048
#define H_DIM 16
#define C_DIM 128

// ---------------- scratch (device globals; no runtime allocation) ----------
__device__ __align__(128) float g_qkv[(size_t)T_DIM * 3 * D_DIM];          // 50 MB
__device__ __align__(128) float g_q [(size_t)H_DIM * T_DIM * C_DIM];
__device__ __align__(128) float g_k [(size_t)H_DIM * T_DIM * C_DIM];
__device__ __align__(128) float g_v [(size_t)H_DIM * T_DIM * C_DIM];
__device__ __align__(128) float g_ao[(size_t)T_DIM * D_DIM];
__device__ __align__(128) __nv_bfloat16 g_xh [(size_t)T_DIM * D_DIM];
__device__ __align__(128) __nv_bfloat16 g_xl [(size_t)T_DIM * D_DIM];
__device__ __align__(128) __nv_bfloat16 g_wah[(size_t)3 * D_DIM * D_DIM];
__device__ __align__(128) __nv_bfloat16 g_wal[(size_t)3 * D_DIM * D_DIM];
__device__ __align__(128) __nv_bfloat16 g_wph[(size_t)D_DIM * D_DIM];
__device__ __align__(128) __nv_bfloat16 g_wpl[(size_t)D_DIM * D_DIM];
__device__ __align__(128) __nv_bfloat16 g_aoh[(size_t)T_DIM * D_DIM];
__device__ __align__(128) __nv_bfloat16 g_aol[(size_t)T_DIM * D_DIM];

// ---------------- small asm helpers ----------------------------------------
__device__ __forceinline__ uint32_t smem_u32(const void* p) {
    return (uint32_t)__cvta_generic_to_shared(p);
}
__device__ __forceinline__ void cpa16(void* s, const void* g) {
    asm volatile("cp.async.cg.shared.global [%0], [%1], 16;\n"
                 :: "r"(smem_u32(s)), "l"(g));
}
__device__ __forceinline__ void cpa_commit() {
    asm volatile("cp.async.commit_group;\n");
}
__device__ __forceinline__ void ldm_x4(uint32_t& d0, uint32_t& d1,
                                       uint32_t& d2, uint32_t& d3,
                                       const void* p) {
    asm volatile("ldmatrix.sync.aligned.m8n8.x4.shared.b16 {%0,%1,%2,%3}, [%4];\n"
                 : "=r"(d0), "=r"(d1), "=r"(d2), "=r"(d3)
                 : "r"(smem_u32(p)));
}
__device__ __forceinline__ void mma16816(float* c, const uint32_t* a,
                                         const uint32_t* b) {
    asm volatile("mma.sync.aligned.m16n8k16.row.col.f32.bf16.bf16.f32 "
                 "{%0,%1,%2,%3}, {%4,%5,%6,%7}, {%8,%9}, {%0,%1,%2,%3};\n"
                 : "+f"(c[0]), "+f"(c[1]), "+f"(c[2]), "+f"(c[3])
                 : "r"(a[0]), "r"(a[1]), "r"(a[2]), "r"(a[3]),
                   "r"(b[0]), "r"(b[1]));
}

// ---------------- fp32 -> bf16 (hi, lo) conversion --------------------------
__global__ __launch_bounds__(256)
void cvt_kernel(const float4* __restrict__ src,
                __nv_bfloat162* __restrict__ hi,
                __nv_bfloat162* __restrict__ lo, int n4)
{
    int i = blockIdx.x * 256 + threadIdx.x;
    if (i >= n4) return;
    float4 v = src[i];
    __nv_bfloat16 h0 = __float2bfloat16_rn(v.x);
    __nv_bfloat16 h1 = __float2bfloat16_rn(v.y);
    __nv_bfloat16 h2 = __float2bfloat16_rn(v.z);
    __nv_bfloat16 h3 = __float2bfloat16_rn(v.w);
    __nv_bfloat16 l0 = __float2bfloat16_rn(v.x - __bfloat162float(h0));
    __nv_bfloat16 l1 = __float2bfloat16_rn(v.y - __bfloat162float(h1));
    __nv_bfloat16 l2 = __float2bfloat16_rn(v.z - __bfloat162float(h2));
    __nv_bfloat16 l3 = __float2bfloat16_rn(v.w - __bfloat162float(h3));
    __nv_bfloat162 a; a.x = h0; a.y = h1;
    __nv_bfloat162 b; b.x = h2; b.y = h3;
    __nv_bfloat162 c; c.x = l0; c.y = l1;
    __nv_bfloat162 d; d.x = l2; d.y = l3;
    hi[2 * i] = a; hi[2 * i + 1] = b;
    lo[2 * i] = c; lo[2 * i + 1] = d;
}

// ---------------- bf16x3 NT GEMM (tensor cores) -----------------------------
// C[m,n] = sum_k (Ah+Al)[m,k]*(Bh+Bl)[n,k] + bias[n]  (3 HMMA passes)
// Block 128x128, BK=32, 8 warps (2x4), warp tile 64x32. lda=ldb=K, ldc=N.
// 3-stage cp.async pipeline, dynamic smem, 2 CTAs/SM (<=128 regs).
#define GSTG 32768   // Ah(8K) Al(8K) Bh(8K) Bl(8K) per stage
#define GEMM_STAGES 3
#define GEMM_SMEM (GEMM_STAGES * GSTG)

__device__ __forceinline__ void gemm_pass(const char* sA, const char* sB,
                                          float acc[4][4][4],
                                          int wm, int wn, int lane)
{
#pragma unroll
    for (int ks = 0; ks < 2; ks++) {
        uint32_t af[4][4];
#pragma unroll
        for (int im = 0; im < 4; im++) {
            int r  = wm * 64 + im * 16 + ((lane >> 3) & 1) * 8 + (lane & 7);
            int ch = 2 * ks + (lane >> 4);
            ldm_x4(af[im][0], af[im][1], af[im][2], af[im][3],
                   sA + r * 64 + ((ch ^ ((r >> 1) & 3)) << 4));
        }
        uint32_t bf_[4][2];
#pragma unroll
        for (int ip = 0; ip < 2; ip++) {
            int r  = wn * 32 + ip * 16 + ((lane >> 3) & 1) * 8 + (lane & 7);
            int ch = 2 * ks + (lane >> 4);
            uint32_t r0, r1, r2, r3;
            ldm_x4(r0, r1, r2, r3,
                   sB + r * 64 + ((ch ^ ((r >> 1) & 3)) << 4));
            bf_[2 * ip][0] = r0; bf_[2 * ip + 1][0] = r1;
            bf_[2 * ip][1] = r2; bf_[2 * ip + 1][1] = r3;
        }
#pragma unroll
        for (int im = 0; im < 4; im++)
#pragma unroll
            for (int in = 0; in < 4; in++)
                mma16816(acc[im][in], af[im], bf_[in]);
    }
}

__global__ __launch_bounds__(256, 2)
void mma_gemm_nt(const __nv_bfloat16* __restrict__ Ah,
                 const __nv_bfloat16* __restrict__ Al,
                 const __nv_bfloat16* __restrict__ Bh,
                 const __nv_bfloat16* __restrict__ Bl,
                 float* __restrict__ C,
                 const float* __restrict__ bias,
                 int N, int K)
{
    extern __shared__ __align__(16) char smem_dyn[];

    const int tid  = threadIdx.x;
    const int wid  = tid >> 5, lane = tid & 31;
    const int wm   = wid >> 2, wn = wid & 3;
    const int m0   = blockIdx.y * 128, n0 = blockIdx.x * 128;

    // per-thread fixed load slots (2 x 16B per buffer quarter)
    const int c0_  = tid,        r0_ = c0_ >> 2, j0_ = c0_ & 3;
    const int c1_  = tid + 256,  r1_ = c1_ >> 2, j1_ = c1_ & 3;
    const int off0 = r0_ * 64 + ((j0_ ^ ((r0_ >> 1) & 3)) << 4);
    const int off1 = r1_ * 64 + ((j1_ ^ ((r1_ >> 1) & 3)) << 4);

    float acc[4][4][4];
#pragma unroll
    for (int a = 0; a < 4; a++)
#pragma unroll
        for (int b = 0; b < 4; b++)
#pragma unroll
            for (int c = 0; c < 4; c++) acc[a][b][c] = 0.f;

    const int niter = K / 32;

    auto load_stage = [&](char* s, int k0) {
        size_t ga0 = (size_t)(m0 + r0_) * K + k0 + j0_ * 8;
        size_t gb0 = (size_t)(n0 + r0_) * K + k0 + j0_ * 8;
        size_t ga1 = (size_t)(m0 + r1_) * K + k0 + j1_ * 8;
        size_t gb1 = (size_t)(n0 + r1_) * K + k0 + j1_ * 8;
        cpa16(s + off0,         Ah + ga0);
        cpa16(s + 8192 + off0,  Al + ga0);
        cpa16(s + 16384 + off0, Bh + gb0);
        cpa16(s + 24576 + off0, Bl + gb0);
        cpa16(s + off1,         Ah + ga1);
        cpa16(s + 8192 + off1,  Al + ga1);
        cpa16(s + 16384 + off1, Bh + gb1);
        cpa16(s + 24576 + off1, Bl + gb1);
    };

    // prologue: stages 0, 1  (K = 2048 -> niter = 64 >= 2 always)
    load_stage(smem_dyn, 0);             cpa_commit();
    load_stage(smem_dyn + GSTG, 32);     cpa_commit();

    for (int i = 0; i < niter; i++) {
        if (i + 1 < niter)
            asm volatile("cp.async.wait_group 1;\n");
        else
            asm volatile("cp.async.wait_group 0;\n");
        __syncthreads();
        const char* s = smem_dyn + (size_t)(i % GEMM_STAGES) * GSTG;
        gemm_pass(s,        s + 16384, acc, wm, wn, lane);  // Ah*Bh
        gemm_pass(s + 8192, s + 16384, acc, wm, wn, lane);  // Al*Bh
        gemm_pass(s,        s + 24576, acc, wm, wn, lane);  // Ah*Bl
        __syncthreads();
        if (i + 2 < niter) {
            load_stage(smem_dyn + (size_t)((i + 2) % GEMM_STAGES) * GSTG,
                       (i + 2) * 32);
            cpa_commit();
        }
    }

    // epilogue
#pragma unroll
    for (int im = 0; im < 4; im++) {
        int row = m0 + wm * 64 + im * 16 + (lane >> 2);
#pragma unroll
        for (int in = 0; in < 4; in++) {
            int col = n0 + wn * 32 + in * 8 + 2 * (lane & 3);
            float b0 = bias[col], b1 = bias[col + 1];
            float2 o0, o1;
            o0.x = acc[im][in][0] + b0; o0.y = acc[im][in][1] + b1;
            o1.x = acc[im][in][2] + b0; o1.y = acc[im][in][3] + b1;
            *(float2*)(C + (size_t)row * N + col)       = o0;
            *(float2*)(C + (size_t)(row + 8) * N + col) = o1;
        }
    }
}

// ---------------- LayerNorm + RoPE ------------------------------------------
__global__ __launch_bounds__(128)
void lnrope_kernel(const float* __restrict__ qkv,
                   const float* __restrict__ qw,
                   const float* __restrict__ kw,
                   float* __restrict__ Q, float* __restrict__ Ko,
                   float* __restrict__ V)
{
    const int t = blockIdx.x, h = blockIdx.y, c = threadIdx.x;
    const size_t base = (size_t)t * (3 * D_DIM) + (size_t)h * C_DIM + c;
    const float qv = qkv[base];
    const float kv = qkv[base + D_DIM];
    const float vv = qkv[base + 2 * D_DIM];

    __shared__ float red[4][4];
    float s0 = qv, s1 = qv * qv, s2 = kv, s3 = kv * kv;
#pragma unroll
    for (int o = 16; o; o >>= 1) {
        s0 += __shfl_xor_sync(0xffffffffu, s0, o);
        s1 += __shfl_xor_sync(0xffffffffu, s1, o);
        s2 += __shfl_xor_sync(0xffffffffu, s2, o);
        s3 += __shfl_xor_sync(0xffffffffu, s3, o);
    }
    const int w = c >> 5;
    if ((c & 31) == 0) { red[w][0] = s0; red[w][1] = s1; red[w][2] = s2; red[w][3] = s3; }
    __syncthreads();
    s0 = red[0][0] + red[1][0] + red[2][0] + red[3][0];
    s1 = red[0][1] + red[1][1] + red[2][1] + red[3][1];
    s2 = red[0][2] + red[1][2] + red[2][2] + red[3][2];
    s3 = red[0][3] + red[1][3] + red[2][3] + red[3][3];

    const float inv_n = 1.0f / (float)C_DIM;
    const float muq = s0 * inv_n, muk = s2 * inv_n;
    const float varq = s1 * inv_n - muq * muq;
    const float vark = s3 * inv_n - muk * muk;
    const float qn = (qv - muq) * rsqrtf(varq + 1e-6f) * qw[c];
    const float kn = (kv - muk) * rsqrtf(vark + 1e-6f) * kw[c];

    __shared__ float qs[C_DIM], ks[C_DIM];
    qs[c] = qn; ks[c] = kn;
    __syncthreads();

    const int i = c >> 1;
    const float inv_freq = powf(10000.f, -(float)(2 * i) / (float)C_DIM);
    float sn, cs;
    sincosf((float)t * inv_freq, &sn, &cs);
    const float qrot = (c & 1) ? qs[c - 1] : -qs[c + 1];
    const float krot = (c & 1) ? ks[c - 1] : -ks[c + 1];

    const size_t o = ((size_t)h * T_DIM + t) * C_DIM + c;
    Q[o]  = qn * cs + qrot * sn;
    Ko[o] = kn * cs + krot * sn;
    V[o]  = vv;
}

// ---------------- fused causal flash attention v3 ---------------------------
// FQ=128 q-rows, FKT=128 kv-rows, 512 threads (16 warps), 8x4 register tiles.
// tx = tid&31 (4 cols), ty = tid>>5 = warp id (8 rows) -> warp-uniform rows.
// smem: Qs(64K plain) + Ks(64K swizzled; reused for P) + Vs(64K plain).
#define FLASH2_SMEM (3 * 128 * 128 * 4)

__global__ __launch_bounds__(512, 1)
void flash2_kernel(const float* __restrict__ Qg, const float* __restrict__ Kg,
                   const float* __restrict__ Vg, float* __restrict__ Og)
{
    extern __shared__ float sm[];
    float* Qs = sm;                 // [128][128]
    float* Ks = sm + 16384;         // [128][128] swizzled; doubles as P
    float* Vs = sm + 32768;         // [128][128]

    // heavy tiles first (causal imbalance)
    const int m0 = (gridDim.x - 1 - blockIdx.x) * 128;
    const int h  = blockIdx.y;
    const float scale = 0.08838834764831845f;  // 1/sqrt(128)

    const float4* Q4 = (const float4*)(Qg + (size_t)h * T_DIM * C_DIM);
    const float4* K4 = (const float4*)(Kg + (size_t)h * T_DIM * C_DIM);
    const float4* V4 = (const float4*)(Vg + (size_t)h * T_DIM * C_DIM);

    const int tid = threadIdx.x;
    const int tx  = tid & 31;        // 4 cols each
    const int ty  = tid >> 5;        // 8 rows each (= warp id)

    // load + pre-scale Q (plain layout): 4096 float4 over 512 threads
#pragma unroll
    for (int i = 0; i < 8; i++) {
        int idx = tid + i * 512;
        float4 v = Q4[m0 * 32 + idx];
        v.x *= scale; v.y *= scale; v.z *= scale; v.w *= scale;
        ((float4*)Qs)[idx] = v;
    }

    float Oa[8][4];
#pragma unroll
    for (int r = 0; r < 8; r++)
#pragma unroll
        for (int c = 0; c < 4; c++) Oa[r][c] = 0.f;
    float mr[8], lr[8];
#pragma unroll
    for (int r = 0; r < 8; r++) { mr[r] = -1e30f; lr[r] = 0.f; }

    const int keyA = (2 * ty) & 7;       // swizzle key, rows ty*8..+3
    const int keyB = (2 * ty + 1) & 7;   // rows ty*8+4..+7

    for (int kt = 0; kt <= m0; kt += 128) {
        __syncthreads();   // prior PV reads of Ks/Vs complete
#pragma unroll
        for (int i = 0; i < 8; i++) {
            int idx = tid + i * 512;
            int row = idx >> 5, j32 = idx & 31;
            ((float4*)Ks)[row * 32 + (j32 ^ ((row >> 2) & 7))] = K4[kt * 32 + idx];
            ((float4*)Vs)[idx] = V4[kt * 32 + idx];
        }
        __syncthreads();

        // S = Q . K^T   (8 rows x 4 cols per thread)
        float s[8][4];
#pragma unroll
        for (int r = 0; r < 8; r++)
#pragma unroll
            for (int c = 0; c < 4; c++) s[r][c] = 0.f;

        for (int kk = 0; kk < 128; kk += 4) {
            // K rows tx*4+c; swizzle key = ((tx*4+c)>>2)&7 = tx&7
            const int sw = (((kk >> 2) ^ (tx & 7)) << 2);
            float4 kv[4];
#pragma unroll
            for (int c = 0; c < 4; c++)
                kv[c] = *(const float4*)(Ks + (tx * 4 + c) * 128 + sw);
#pragma unroll
            for (int r = 0; r < 8; r++) {
                float4 qv = *(const float4*)(Qs + (ty * 8 + r) * 128 + kk);
#pragma unroll
                for (int c = 0; c < 4; c++)
                    s[r][c] += qv.x * kv[c].x + qv.y * kv[c].y
                             + qv.z * kv[c].z + qv.w * kv[c].w;
            }
        }

        if (kt == m0) {
#pragma unroll
            for (int r = 0; r < 8; r++)
#pragma unroll
                for (int c = 0; c < 4; c++)
                    if (tx * 4 + c > ty * 8 + r) s[r][c] = -1e30f;
        }

        // online softmax: full-warp row reductions (all 32 lanes share rows)
#pragma unroll
        for (int r = 0; r < 8; r++) {
            float rm = fmaxf(fmaxf(s[r][0], s[r][1]), fmaxf(s[r][2], s[r][3]));
#pragma unroll
            for (int o = 16; o; o >>= 1)
                rm = fmaxf(rm, __shfl_xor_sync(0xffffffffu, rm, o));
            const float nm = fmaxf(mr[r], rm);
            const float al = __expf(mr[r] - nm);
            float rs = 0.f;
#pragma unroll
            for (int c = 0; c < 4; c++) {
                const float p = __expf(s[r][c] - nm);
                s[r][c] = p;
                rs += p;
            }
#pragma unroll
            for (int o = 16; o; o >>= 1)
                rs += __shfl_xor_sync(0xffffffffu, rs, o);
            lr[r] = lr[r] * al + rs;
            mr[r] = nm;
#pragma unroll
            for (int c = 0; c < 4; c++) Oa[r][c] *= al;
        }
        __syncthreads();   // all S reads of Ks done

        // write P over Ks: P[qrow][chunk tx], swizzled chunk = tx ^ key(qrow)
#pragma unroll
        for (int r = 0; r < 8; r++) {
            const int qrow = ty * 8 + r;
            const int key  = (r < 4) ? keyA : keyB;
            float4 p;
            p.x = s[r][0]; p.y = s[r][1]; p.z = s[r][2]; p.w = s[r][3];
            *(float4*)(Ks + qrow * 128 + ((tx ^ key) << 2)) = p;
        }
        __syncthreads();

        // O += P . V   (V plain: lanes cover a 512B row; P broadcast)
        for (int j = 0; j < 128; j++) {
            float4 v0 = *(const float4*)(Vs + j * 128 + tx * 4);
            const int swA = (((j >> 2) ^ keyA) << 2) + (j & 3);
            const int swB = (((j >> 2) ^ keyB) << 2) + (j & 3);
#pragma unroll
            for (int r = 0; r < 8; r++) {
                const float p = Ks[(ty * 8 + r) * 128 + ((r < 4) ? swA : swB)];
                Oa[r][0] += p * v0.x; Oa[r][1] += p * v0.y;
                Oa[r][2] += p * v0.z; Oa[r][3] += p * v0.w;
            }
        }
    }

    // normalize + store [T, D] at column h*C
#pragma unroll
    for (int r = 0; r < 8; r++) {
        const float inv = 1.f / lr[r];
        const size_t row = (size_t)(m0 + ty * 8 + r);
        float4 o;
        o.x = Oa[r][0] * inv; o.y = Oa[r][1] * inv;
        o.z = Oa[r][2] * inv; o.w = Oa[r][3] * inv;
        *(float4*)(Og + row * D_DIM + h * C_DIM + tx * 4) = o;
    }
}

// ---------------------------------------------------------------------------
extern "C" void kernel_launch(void* const* d_in, const int* in_sizes, int n_in,
                              void* d_out, int out_size)
{
    const float* x      = (const float*)d_in[0];
    const float* W_attn = (const float*)d_in[1];
    const float* b_attn = (const float*)d_in[2];
    const float* W_proj = (const float*)d_in[3];
    const float* b_proj = (const float*)d_in[4];
    const float* q_ln_w = (const float*)d_in[5];
    const float* k_ln_w = (const float*)d_in[6];
    float* out = (float*)d_out;

    float *qkv, *q, *k, *v, *ao;
    __nv_bfloat16 *xh, *xl, *wah, *wal, *wph, *wpl, *aoh, *aol;
    cudaGetSymbolAddress((void**)&qkv, g_qkv);
    cudaGetSymbolAddress((void**)&q,   g_q);
    cudaGetSymbolAddress((void**)&k,   g_k);
    cudaGetSymbolAddress((void**)&v,   g_v);
    cudaGetSymbolAddress((void**)&ao,  g_ao);
    cudaGetSymbolAddress((void**)&xh,  g_xh);
    cudaGetSymbolAddress((void**)&xl,  g_xl);
    cudaGetSymbolAddress((void**)&wah, g_wah);
    cudaGetSymbolAddress((void**)&wal, g_wal);
    cudaGetSymbolAddress((void**)&wph, g_wph);
    cudaGetSymbolAddress((void**)&wpl, g_wpl);
    cudaGetSymbolAddress((void**)&aoh, g_aoh);
    cudaGetSymbolAddress((void**)&aol, g_aol);

    cudaFuncSetAttribute(mma_gemm_nt,
                         cudaFuncAttributeMaxDynamicSharedMemorySize,
                         GEMM_SMEM);
    cudaFuncSetAttribute(flash2_kernel,
                         cudaFuncAttributeMaxDynamicSharedMemorySize,
                         FLASH2_SMEM);

    const int n4_x  = T_DIM * D_DIM / 4;
    const int n4_wa = 3 * D_DIM * D_DIM / 4;
    const int n4_wp = D_DIM * D_DIM / 4;

    // 0) split fp32 -> bf16 hi/lo
    cvt_kernel<<<n4_x  / 256, 256>>>((const float4*)x,      (__nv_bfloat162*)xh,  (__nv_bfloat162*)xl,  n4_x);
    cvt_kernel<<<n4_wa / 256, 256>>>((const float4*)W_attn, (__nv_bfloat162*)wah, (__nv_bfloat162*)wal, n4_wa);
    cvt_kernel<<<n4_wp / 256, 256>>>((const float4*)W_proj, (__nv_bfloat162*)wph, (__nv_bfloat162*)wpl, n4_wp);

    // 1) QKV = x @ W_attn^T + b_attn   (tensor cores, bf16x3)
    mma_gemm_nt<<<dim3(3 * D_DIM / 128, T_DIM / 128), 256, GEMM_SMEM>>>(
        xh, xl, wah, wal, qkv, b_attn, 3 * D_DIM, D_DIM);

    // 2) per-head LayerNorm + RoPE
    lnrope_kernel<<<dim3(T_DIM, H_DIM), 128>>>(qkv, q_ln_w, k_ln_w, q, k, v);

    // 3) fused causal attention -> ao [T, D]
    flash2_kernel<<<dim3(T_DIM / 128, H_DIM), 512, FLASH2_SMEM>>>(q, k, v, ao);

    // 4) split ao, then out = ao @ W_proj^T + b_proj
    cvt_kernel<<<n4_x / 256, 256>>>((const float4*)ao, (__nv_bfloat162*)aoh, (__nv_bfloat162*)aol, n4_x);
    mma_gemm_nt<<<dim3(D_DIM / 128, T_DIM / 128), 256, GEMM_SMEM>>>(
        aoh, aol, wph, wpl, out, b_proj, D_DIM, D_DIM);
}

// round 7
// speedup vs baseline: 1.5973x; 1.5973x over previous
#include <cuda_runtime.h>
#include <cuda_bf16.h>
#include <math.h>
#include <stdint.h>
#include <stddef.h>

#define T_DIM 2048
#define D_DIM 2048
#define H_DIM 16
#define C_DIM 128

// ---------------- scratch (device globals; no runtime allocation) ----------
__device__ __align__(128) float g_qkv[(size_t)T_DIM * 3 * D_DIM];
__device__ __align__(128) float g_ao [(size_t)T_DIM * D_DIM];
__device__ __align__(128) __nv_bfloat16 g_xh [(size_t)T_DIM * D_DIM];
__device__ __align__(128) __nv_bfloat16 g_xl [(size_t)T_DIM * D_DIM];
__device__ __align__(128) __nv_bfloat16 g_wah[(size_t)3 * D_DIM * D_DIM];
__device__ __align__(128) __nv_bfloat16 g_wal[(size_t)3 * D_DIM * D_DIM];
__device__ __align__(128) __nv_bfloat16 g_wph[(size_t)D_DIM * D_DIM];
__device__ __align__(128) __nv_bfloat16 g_wpl[(size_t)D_DIM * D_DIM];
__device__ __align__(128) __nv_bfloat16 g_aoh[(size_t)T_DIM * D_DIM];
__device__ __align__(128) __nv_bfloat16 g_aol[(size_t)T_DIM * D_DIM];
// bf16 hi/lo Q (pre-scaled), K, V in [H, T, C]
__device__ __align__(128) __nv_bfloat16 g_qh[(size_t)H_DIM * T_DIM * C_DIM];
__device__ __align__(128) __nv_bfloat16 g_ql[(size_t)H_DIM * T_DIM * C_DIM];
__device__ __align__(128) __nv_bfloat16 g_kh[(size_t)H_DIM * T_DIM * C_DIM];
__device__ __align__(128) __nv_bfloat16 g_kl[(size_t)H_DIM * T_DIM * C_DIM];
__device__ __align__(128) __nv_bfloat16 g_vh[(size_t)H_DIM * T_DIM * C_DIM];
__device__ __align__(128) __nv_bfloat16 g_vl[(size_t)H_DIM * T_DIM * C_DIM];

// ---------------- asm helpers ----------------------------------------------
__device__ __forceinline__ uint32_t smem_u32(const void* p) {
    return (uint32_t)__cvta_generic_to_shared(p);
}
__device__ __forceinline__ void cpa16(void* s, const void* g) {
    asm volatile("cp.async.cg.shared.global [%0], [%1], 16;\n"
                 :: "r"(smem_u32(s)), "l"(g));
}
__device__ __forceinline__ void cpa_commit() {
    asm volatile("cp.async.commit_group;\n");
}
__device__ __forceinline__ void ldm_x4(uint32_t& d0, uint32_t& d1,
                                       uint32_t& d2, uint32_t& d3,
                                       const void* p) {
    asm volatile("ldmatrix.sync.aligned.m8n8.x4.shared.b16 {%0,%1,%2,%3}, [%4];\n"
                 : "=r"(d0), "=r"(d1), "=r"(d2), "=r"(d3)
                 : "r"(smem_u32(p)));
}
__device__ __forceinline__ void ldm_x4_t(uint32_t& d0, uint32_t& d1,
                                         uint32_t& d2, uint32_t& d3,
                                         const void* p) {
    asm volatile("ldmatrix.sync.aligned.m8n8.x4.trans.shared.b16 {%0,%1,%2,%3}, [%4];\n"
                 : "=r"(d0), "=r"(d1), "=r"(d2), "=r"(d3)
                 : "r"(smem_u32(p)));
}
__device__ __forceinline__ void mma16816(float* c, const uint32_t* a,
                                         const uint32_t* b) {
    asm volatile("mma.sync.aligned.m16n8k16.row.col.f32.bf16.bf16.f32 "
                 "{%0,%1,%2,%3}, {%4,%5,%6,%7}, {%8,%9}, {%0,%1,%2,%3};\n"
                 : "+f"(c[0]), "+f"(c[1]), "+f"(c[2]), "+f"(c[3])
                 : "r"(a[0]), "r"(a[1]), "r"(a[2]), "r"(a[3]),
                   "r"(b[0]), "r"(b[1]));
}
__device__ __forceinline__ uint32_t pack_hi(float a, float b) {
    __nv_bfloat162 v = __float22bfloat162_rn(make_float2(a, b));
    return *(uint32_t*)&v;
}
__device__ __forceinline__ uint32_t pack_lo(float a, float b) {
    float ra = a - __bfloat162float(__float2bfloat16_rn(a));
    float rb = b - __bfloat162float(__float2bfloat16_rn(b));
    __nv_bfloat162 v = __float22bfloat162_rn(make_float2(ra, rb));
    return *(uint32_t*)&v;
}

// ---------------- fp32 -> bf16 (hi, lo) conversion --------------------------
__global__ __launch_bounds__(256)
void cvt_kernel(const float4* __restrict__ src,
                __nv_bfloat162* __restrict__ hi,
                __nv_bfloat162* __restrict__ lo, int n4)
{
    int i = blockIdx.x * 256 + threadIdx.x;
    if (i >= n4) return;
    float4 v = src[i];
    __nv_bfloat16 h0 = __float2bfloat16_rn(v.x);
    __nv_bfloat16 h1 = __float2bfloat16_rn(v.y);
    __nv_bfloat16 h2 = __float2bfloat16_rn(v.z);
    __nv_bfloat16 h3 = __float2bfloat16_rn(v.w);
    __nv_bfloat16 l0 = __float2bfloat16_rn(v.x - __bfloat162float(h0));
    __nv_bfloat16 l1 = __float2bfloat16_rn(v.y - __bfloat162float(h1));
    __nv_bfloat16 l2 = __float2bfloat16_rn(v.z - __bfloat162float(h2));
    __nv_bfloat16 l3 = __float2bfloat16_rn(v.w - __bfloat162float(h3));
    __nv_bfloat162 a; a.x = h0; a.y = h1;
    __nv_bfloat162 b; b.x = h2; b.y = h3;
    __nv_bfloat162 c; c.x = l0; c.y = l1;
    __nv_bfloat162 d; d.x = l2; d.y = l3;
    hi[2 * i] = a; hi[2 * i + 1] = b;
    lo[2 * i] = c; lo[2 * i + 1] = d;
}

// ---------------- bf16x3 NT GEMM (tensor cores) -----------------------------
#define GSTG 32768
#define GEMM_STAGES 3
#define GEMM_SMEM (GEMM_STAGES * GSTG)

__device__ __forceinline__ void gemm_pass(const char* sA, const char* sB,
                                          float acc[4][4][4],
                                          int wm, int wn, int lane)
{
#pragma unroll
    for (int ks = 0; ks < 2; ks++) {
        uint32_t af[4][4];
#pragma unroll
        for (int im = 0; im < 4; im++) {
            int r  = wm * 64 + im * 16 + ((lane >> 3) & 1) * 8 + (lane & 7);
            int ch = 2 * ks + (lane >> 4);
            ldm_x4(af[im][0], af[im][1], af[im][2], af[im][3],
                   sA + r * 64 + ((ch ^ ((r >> 1) & 3)) << 4));
        }
        uint32_t bf_[4][2];
#pragma unroll
        for (int ip = 0; ip < 2; ip++) {
            int r  = wn * 32 + ip * 16 + ((lane >> 3) & 1) * 8 + (lane & 7);
            int ch = 2 * ks + (lane >> 4);
            uint32_t r0, r1, r2, r3;
            ldm_x4(r0, r1, r2, r3,
                   sB + r * 64 + ((ch ^ ((r >> 1) & 3)) << 4));
            bf_[2 * ip][0] = r0; bf_[2 * ip + 1][0] = r1;
            bf_[2 * ip][1] = r2; bf_[2 * ip + 1][1] = r3;
        }
#pragma unroll
        for (int im = 0; im < 4; im++)
#pragma unroll
            for (int in = 0; in < 4; in++)
                mma16816(acc[im][in], af[im], bf_[in]);
    }
}

__global__ __launch_bounds__(256, 2)
void mma_gemm_nt(const __nv_bfloat16* __restrict__ Ah,
                 const __nv_bfloat16* __restrict__ Al,
                 const __nv_bfloat16* __restrict__ Bh,
                 const __nv_bfloat16* __restrict__ Bl,
                 float* __restrict__ C,
                 const float* __restrict__ bias,
                 int N, int K)
{
    extern __shared__ __align__(16) char smem_dyn[];

    const int tid  = threadIdx.x;
    const int wid  = tid >> 5, lane = tid & 31;
    const int wm   = wid >> 2, wn = wid & 3;
    const int m0   = blockIdx.y * 128, n0 = blockIdx.x * 128;

    const int c0_  = tid,        r0_ = c0_ >> 2, j0_ = c0_ & 3;
    const int c1_  = tid + 256,  r1_ = c1_ >> 2, j1_ = c1_ & 3;
    const int off0 = r0_ * 64 + ((j0_ ^ ((r0_ >> 1) & 3)) << 4);
    const int off1 = r1_ * 64 + ((j1_ ^ ((r1_ >> 1) & 3)) << 4);

    float acc[4][4][4];
#pragma unroll
    for (int a = 0; a < 4; a++)
#pragma unroll
        for (int b = 0; b < 4; b++)
#pragma unroll
            for (int c = 0; c < 4; c++) acc[a][b][c] = 0.f;

    const int niter = K / 32;

    auto load_stage = [&](char* s, int k0) {
        size_t ga0 = (size_t)(m0 + r0_) * K + k0 + j0_ * 8;
        size_t gb0 = (size_t)(n0 + r0_) * K + k0 + j0_ * 8;
        size_t ga1 = (size_t)(m0 + r1_) * K + k0 + j1_ * 8;
        size_t gb1 = (size_t)(n0 + r1_) * K + k0 + j1_ * 8;
        cpa16(s + off0,         Ah + ga0);
        cpa16(s + 8192 + off0,  Al + ga0);
        cpa16(s + 16384 + off0, Bh + gb0);
        cpa16(s + 24576 + off0, Bl + gb0);
        cpa16(s + off1,         Ah + ga1);
        cpa16(s + 8192 + off1,  Al + ga1);
        cpa16(s + 16384 + off1, Bh + gb1);
        cpa16(s + 24576 + off1, Bl + gb1);
    };

    load_stage(smem_dyn, 0);             cpa_commit();
    load_stage(smem_dyn + GSTG, 32);     cpa_commit();

    for (int i = 0; i < niter; i++) {
        if (i + 1 < niter)
            asm volatile("cp.async.wait_group 1;\n");
        else
            asm volatile("cp.async.wait_group 0;\n");
        __syncthreads();
        const char* s = smem_dyn + (size_t)(i % GEMM_STAGES) * GSTG;
        gemm_pass(s,        s + 16384, acc, wm, wn, lane);
        gemm_pass(s + 8192, s + 16384, acc, wm, wn, lane);
        gemm_pass(s,        s + 24576, acc, wm, wn, lane);
        __syncthreads();
        if (i + 2 < niter) {
            load_stage(smem_dyn + (size_t)((i + 2) % GEMM_STAGES) * GSTG,
                       (i + 2) * 32);
            cpa_commit();
        }
    }

#pragma unroll
    for (int im = 0; im < 4; im++) {
        int row = m0 + wm * 64 + im * 16 + (lane >> 2);
#pragma unroll
        for (int in = 0; in < 4; in++) {
            int col = n0 + wn * 32 + in * 8 + 2 * (lane & 3);
            float b0 = bias[col], b1 = bias[col + 1];
            float2 o0, o1;
            o0.x = acc[im][in][0] + b0; o0.y = acc[im][in][1] + b1;
            o1.x = acc[im][in][2] + b0; o1.y = acc[im][in][3] + b1;
            *(float2*)(C + (size_t)row * N + col)       = o0;
            *(float2*)(C + (size_t)(row + 8) * N + col) = o1;
        }
    }
}

// ---------------- LayerNorm + RoPE -> bf16 hi/lo Q(scaled), K, V ------------
__global__ __launch_bounds__(128)
void lnrope_kernel(const float* __restrict__ qkv,
                   const float* __restrict__ qw,
                   const float* __restrict__ kw,
                   __nv_bfloat16* __restrict__ Qh, __nv_bfloat16* __restrict__ Ql,
                   __nv_bfloat16* __restrict__ Kh, __nv_bfloat16* __restrict__ Kl,
                   __nv_bfloat16* __restrict__ Vh, __nv_bfloat16* __restrict__ Vl)
{
    const int t = blockIdx.x, h = blockIdx.y, c = threadIdx.x;
    const size_t base = (size_t)t * (3 * D_DIM) + (size_t)h * C_DIM + c;
    const float qv = qkv[base];
    const float kv = qkv[base + D_DIM];
    const float vv = qkv[base + 2 * D_DIM];

    __shared__ float red[4][4];
    float s0 = qv, s1 = qv * qv, s2 = kv, s3 = kv * kv;
#pragma unroll
    for (int o = 16; o; o >>= 1) {
        s0 += __shfl_xor_sync(0xffffffffu, s0, o);
        s1 += __shfl_xor_sync(0xffffffffu, s1, o);
        s2 += __shfl_xor_sync(0xffffffffu, s2, o);
        s3 += __shfl_xor_sync(0xffffffffu, s3, o);
    }
    const int w = c >> 5;
    if ((c & 31) == 0) { red[w][0] = s0; red[w][1] = s1; red[w][2] = s2; red[w][3] = s3; }
    __syncthreads();
    s0 = red[0][0] + red[1][0] + red[2][0] + red[3][0];
    s1 = red[0][1] + red[1][1] + red[2][1] + red[3][1];
    s2 = red[0][2] + red[1][2] + red[2][2] + red[3][2];
    s3 = red[0][3] + red[1][3] + red[2][3] + red[3][3];

    const float inv_n = 1.0f / (float)C_DIM;
    const float muq = s0 * inv_n, muk = s2 * inv_n;
    const float varq = s1 * inv_n - muq * muq;
    const float vark = s3 * inv_n - muk * muk;
    const float qn = (qv - muq) * rsqrtf(varq + 1e-6f) * qw[c];
    const float kn = (kv - muk) * rsqrtf(vark + 1e-6f) * kw[c];

    __shared__ float qs[C_DIM], ks[C_DIM];
    qs[c] = qn; ks[c] = kn;
    __syncthreads();

    const int i = c >> 1;
    const float inv_freq = powf(10000.f, -(float)(2 * i) / (float)C_DIM);
    float sn, cs;
    sincosf((float)t * inv_freq, &sn, &cs);
    const float qrot = (c & 1) ? qs[c - 1] : -qs[c + 1];
    const float krot = (c & 1) ? ks[c - 1] : -ks[c + 1];

    const float qsc = (qn * cs + qrot * sn) * 0.08838834764831845f; // /sqrt(C)
    const float ksc = kn * cs + krot * sn;

    const size_t o = ((size_t)h * T_DIM + t) * C_DIM + c;
    __nv_bfloat16 b;
    b = __float2bfloat16_rn(qsc); Qh[o] = b;
    Ql[o] = __float2bfloat16_rn(qsc - __bfloat162float(b));
    b = __float2bfloat16_rn(ksc); Kh[o] = b;
    Kl[o] = __float2bfloat16_rn(ksc - __bfloat162float(b));
    b = __float2bfloat16_rn(vv);  Vh[o] = b;
    Vl[o] = __float2bfloat16_rn(vv - __bfloat162float(b));
}

// ---------------- tensor-core causal flash attention ------------------------
// 256 threads = 8 warps; CTA tile 128 q-rows x 128 kv per iter.
// Warp w owns q-rows [w*16, w*16+16). bf16x3 for S and PV, fp32 online softmax.
// smem: Qh,Ql,Kh,Kl,Vh,Vl tiles, each 128x128 bf16 = 32KB, XOR-swizzled rows.
#define FA_SMEM (6 * 32768)   // 196608

__global__ __launch_bounds__(256, 1)
void fa_kernel(const __nv_bfloat16* __restrict__ Qhg,
               const __nv_bfloat16* __restrict__ Qlg,
               const __nv_bfloat16* __restrict__ Khg,
               const __nv_bfloat16* __restrict__ Klg,
               const __nv_bfloat16* __restrict__ Vhg,
               const __nv_bfloat16* __restrict__ Vlg,
               float* __restrict__ Og)
{
    extern __shared__ __align__(16) char fsm[];
    char* sQh = fsm;
    char* sQl = fsm + 32768;
    char* sKh = fsm + 65536;
    char* sKl = fsm + 98304;
    char* sVh = fsm + 131072;
    char* sVl = fsm + 163840;

    const int m0 = (gridDim.x - 1 - blockIdx.x) * 128;   // heavy tiles first
    const int h  = blockIdx.y;
    const size_t hb = (size_t)h * T_DIM * C_DIM;

    const int tid  = threadIdx.x;
    const int w    = tid >> 5, lane = tid & 31;

    // load Q tiles (hi/lo), swizzled rows (256B row, 16B chunks, ch ^= row&7)
#pragma unroll
    for (int i = 0; i < 8; i++) {
        int c = tid + i * 256;
        int row = c >> 4, ch = c & 15;
        int dst = row * 256 + ((ch ^ (row & 7)) << 4);
        size_t src = hb + (size_t)(m0 + row) * C_DIM + ch * 8;
        cpa16(sQh + dst, Qhg + src);
        cpa16(sQl + dst, Qlg + src);
    }
    cpa_commit();

    float O[16][4];
#pragma unroll
    for (int f = 0; f < 16; f++)
#pragma unroll
        for (int x = 0; x < 4; x++) O[f][x] = 0.f;
    float mrow0 = -1e30f, mrow1 = -1e30f, lrow0 = 0.f, lrow1 = 0.f;

    const int arow = w * 16 + ((lane >> 3) & 1) * 8 + (lane & 7); // ldm A row
    const int achb = lane >> 4;                                    // chunk sel

    for (int kt = 0; kt <= m0; kt += 128) {
        __syncthreads();   // previous tile fully consumed
#pragma unroll
        for (int i = 0; i < 8; i++) {
            int c = tid + i * 256;
            int row = c >> 4, ch = c & 15;
            int dst = row * 256 + ((ch ^ (row & 7)) << 4);
            size_t src = hb + (size_t)(kt + row) * C_DIM + ch * 8;
            cpa16(sKh + dst, Khg + src);
            cpa16(sKl + dst, Klg + src);
            cpa16(sVh + dst, Vhg + src);
            cpa16(sVl + dst, Vlg + src);
        }
        cpa_commit();
        asm volatile("cp.async.wait_group 0;\n");
        __syncthreads();

        // ---- S = Q.K^T (bf16x3), accum fp32: 16 n8-frags over kv 128 ----
        float S[16][4];
#pragma unroll
        for (int f = 0; f < 16; f++)
#pragma unroll
            for (int x = 0; x < 4; x++) S[f][x] = 0.f;

#pragma unroll
        for (int ks = 0; ks < 8; ks++) {
            const int ch = 2 * ks + achb;
            uint32_t aQh[4], aQl[4];
            ldm_x4(aQh[0], aQh[1], aQh[2], aQh[3],
                   sQh + arow * 256 + ((ch ^ (arow & 7)) << 4));
            ldm_x4(aQl[0], aQl[1], aQl[2], aQl[3],
                   sQl + arow * 256 + ((ch ^ (arow & 7)) << 4));
#pragma unroll
            for (int nb = 0; nb < 8; nb++) {
                const int brow = nb * 16 + ((lane >> 3) & 1) * 8 + (lane & 7);
                const int boff = brow * 256 + ((ch ^ (brow & 7)) << 4);
                uint32_t r0, r1, r2, r3;
                ldm_x4(r0, r1, r2, r3, sKh + boff);
                uint32_t blo[2] = {r0, r2}, bhi[2] = {r1, r3};
                mma16816(S[2 * nb],     aQh, blo);
                mma16816(S[2 * nb + 1], aQh, bhi);
                mma16816(S[2 * nb],     aQl, blo);
                mma16816(S[2 * nb + 1], aQl, bhi);
                ldm_x4(r0, r1, r2, r3, sKl + boff);
                uint32_t clo[2] = {r0, r2}, chi[2] = {r1, r3};
                mma16816(S[2 * nb],     aQh, clo);
                mma16816(S[2 * nb + 1], aQh, chi);
            }
        }

        // ---- causal mask (diagonal tile only) ----
        const int row0 = m0 + w * 16 + (lane >> 2);   // row1 = row0 + 8
        if (kt == m0) {
#pragma unroll
            for (int f = 0; f < 16; f++) {
                const int col = kt + f * 8 + 2 * (lane & 3);
                if (col     > row0)     S[f][0] = -1e30f;
                if (col + 1 > row0)     S[f][1] = -1e30f;
                if (col     > row0 + 8) S[f][2] = -1e30f;
                if (col + 1 > row0 + 8) S[f][3] = -1e30f;
            }
        }

        // ---- online softmax (rows live in 4-lane groups) ----
        float mx0 = -1e30f, mx1 = -1e30f;
#pragma unroll
        for (int f = 0; f < 16; f++) {
            mx0 = fmaxf(mx0, fmaxf(S[f][0], S[f][1]));
            mx1 = fmaxf(mx1, fmaxf(S[f][2], S[f][3]));
        }
        mx0 = fmaxf(mx0, __shfl_xor_sync(0xffffffffu, mx0, 1));
        mx0 = fmaxf(mx0, __shfl_xor_sync(0xffffffffu, mx0, 2));
        mx1 = fmaxf(mx1, __shfl_xor_sync(0xffffffffu, mx1, 1));
        mx1 = fmaxf(mx1, __shfl_xor_sync(0xffffffffu, mx1, 2));

        const float nm0 = fmaxf(mrow0, mx0);
        const float nm1 = fmaxf(mrow1, mx1);
        const float al0 = __expf(mrow0 - nm0);
        const float al1 = __expf(mrow1 - nm1);
        mrow0 = nm0; mrow1 = nm1;

        float sum0 = 0.f, sum1 = 0.f;
#pragma unroll
        for (int f = 0; f < 16; f++) {
            S[f][0] = __expf(S[f][0] - nm0);
            S[f][1] = __expf(S[f][1] - nm0);
            S[f][2] = __expf(S[f][2] - nm1);
            S[f][3] = __expf(S[f][3] - nm1);
            sum0 += S[f][0] + S[f][1];
            sum1 += S[f][2] + S[f][3];
        }
        sum0 += __shfl_xor_sync(0xffffffffu, sum0, 1);
        sum0 += __shfl_xor_sync(0xffffffffu, sum0, 2);
        sum1 += __shfl_xor_sync(0xffffffffu, sum1, 1);
        sum1 += __shfl_xor_sync(0xffffffffu, sum1, 2);
        lrow0 = lrow0 * al0 + sum0;
        lrow1 = lrow1 * al1 + sum1;

#pragma unroll
        for (int f = 0; f < 16; f++) {
            O[f][0] *= al0; O[f][1] *= al0;
            O[f][2] *= al1; O[f][3] *= al1;
        }

        // ---- O += P.V (bf16x3 via accumulator->A-fragment repack) ----
#pragma unroll
        for (int kb = 0; kb < 8; kb++) {
            uint32_t aPh[4], aPl[4];
            aPh[0] = pack_hi(S[2 * kb][0],     S[2 * kb][1]);
            aPh[1] = pack_hi(S[2 * kb][2],     S[2 * kb][3]);
            aPh[2] = pack_hi(S[2 * kb + 1][0], S[2 * kb + 1][1]);
            aPh[3] = pack_hi(S[2 * kb + 1][2], S[2 * kb + 1][3]);
            aPl[0] = pack_lo(S[2 * kb][0],     S[2 * kb][1]);
            aPl[1] = pack_lo(S[2 * kb][2],     S[2 * kb][3]);
            aPl[2] = pack_lo(S[2 * kb + 1][0], S[2 * kb + 1][1]);
            aPl[3] = pack_lo(S[2 * kb + 1][2], S[2 * kb + 1][3]);

            const int kvrow = kb * 16 + ((lane >> 3) & 1) * 8 + (lane & 7);
#pragma unroll
            for (int nb = 0; nb < 8; nb++) {
                const int chv  = 2 * nb + (lane >> 4);
                const int voff = kvrow * 256 + ((chv ^ (kvrow & 7)) << 4);
                uint32_t r0, r1, r2, r3;
                ldm_x4_t(r0, r1, r2, r3, sVh + voff);
                uint32_t blo[2] = {r0, r1}, bhi[2] = {r2, r3};
                mma16816(O[2 * nb],     aPh, blo);
                mma16816(O[2 * nb + 1], aPh, bhi);
                mma16816(O[2 * nb],     aPl, blo);
                mma16816(O[2 * nb + 1], aPl, bhi);
                ldm_x4_t(r0, r1, r2, r3, sVl + voff);
                uint32_t clo[2] = {r0, r1}, chi[2] = {r2, r3};
                mma16816(O[2 * nb],     aPh, clo);
                mma16816(O[2 * nb + 1], aPh, chi);
            }
        }
    }

    // ---- normalize + store [T, D] at column h*C ----
    const float inv0 = 1.f / lrow0;
    const float inv1 = 1.f / lrow1;
    const int orow = m0 + w * 16 + (lane >> 2);
#pragma unroll
    for (int f = 0; f < 16; f++) {
        const int col = h * C_DIM + f * 8 + 2 * (lane & 3);
        float2 o0, o1;
        o0.x = O[f][0] * inv0; o0.y = O[f][1] * inv0;
        o1.x = O[f][2] * inv1; o1.y = O[f][3] * inv1;
        *(float2*)(Og + (size_t)orow * D_DIM + col)       = o0;
        *(float2*)(Og + (size_t)(orow + 8) * D_DIM + col) = o1;
    }
}

// ---------------------------------------------------------------------------
extern "C" void kernel_launch(void* const* d_in, const int* in_sizes, int n_in,
                              void* d_out, int out_size)
{
    const float* x      = (const float*)d_in[0];
    const float* W_attn = (const float*)d_in[1];
    const float* b_attn = (const float*)d_in[2];
    const float* W_proj = (const float*)d_in[3];
    const float* b_proj = (const float*)d_in[4];
    const float* q_ln_w = (const float*)d_in[5];
    const float* k_ln_w = (const float*)d_in[6];
    float* out = (float*)d_out;

    float *qkv, *ao;
    __nv_bfloat16 *xh, *xl, *wah, *wal, *wph, *wpl, *aoh, *aol;
    __nv_bfloat16 *qh, *ql, *kh, *kl, *vh, *vl;
    cudaGetSymbolAddress((void**)&qkv, g_qkv);
    cudaGetSymbolAddress((void**)&ao,  g_ao);
    cudaGetSymbolAddress((void**)&xh,  g_xh);
    cudaGetSymbolAddress((void**)&xl,  g_xl);
    cudaGetSymbolAddress((void**)&wah, g_wah);
    cudaGetSymbolAddress((void**)&wal, g_wal);
    cudaGetSymbolAddress((void**)&wph, g_wph);
    cudaGetSymbolAddress((void**)&wpl, g_wpl);
    cudaGetSymbolAddress((void**)&aoh, g_aoh);
    cudaGetSymbolAddress((void**)&aol, g_aol);
    cudaGetSymbolAddress((void**)&qh,  g_qh);
    cudaGetSymbolAddress((void**)&ql,  g_ql);
    cudaGetSymbolAddress((void**)&kh,  g_kh);
    cudaGetSymbolAddress((void**)&kl,  g_kl);
    cudaGetSymbolAddress((void**)&vh,  g_vh);
    cudaGetSymbolAddress((void**)&vl,  g_vl);

    cudaFuncSetAttribute(mma_gemm_nt,
                         cudaFuncAttributeMaxDynamicSharedMemorySize, GEMM_SMEM);
    cudaFuncSetAttribute(fa_kernel,
                         cudaFuncAttributeMaxDynamicSharedMemorySize, FA_SMEM);

    const int n4_x  = T_DIM * D_DIM / 4;
    const int n4_wa = 3 * D_DIM * D_DIM / 4;
    const int n4_wp = D_DIM * D_DIM / 4;

    // 0) split fp32 -> bf16 hi/lo
    cvt_kernel<<<n4_x  / 256, 256>>>((const float4*)x,      (__nv_bfloat162*)xh,  (__nv_bfloat162*)xl,  n4_x);
    cvt_kernel<<<n4_wa / 256, 256>>>((const float4*)W_attn, (__nv_bfloat162*)wah, (__nv_bfloat162*)wal, n4_wa);
    cvt_kernel<<<n4_wp / 256, 256>>>((const float4*)W_proj, (__nv_bfloat162*)wph, (__nv_bfloat162*)wpl, n4_wp);

    // 1) QKV = x @ W_attn^T + b_attn
    mma_gemm_nt<<<dim3(3 * D_DIM / 128, T_DIM / 128), 256, GEMM_SMEM>>>(
        xh, xl, wah, wal, qkv, b_attn, 3 * D_DIM, D_DIM);

    // 2) LayerNorm + RoPE -> bf16 hi/lo Q(scaled), K, V in [H,T,C]
    lnrope_kernel<<<dim3(T_DIM, H_DIM), 128>>>(qkv, q_ln_w, k_ln_w,
                                               qh, ql, kh, kl, vh, vl);

    // 3) tensor-core causal flash attention -> ao [T, D]
    fa_kernel<<<dim3(T_DIM / 128, H_DIM), 256, FA_SMEM>>>(
        qh, ql, kh, kl, vh, vl, ao);

    // 4) split ao, then out = ao @ W_proj^T + b_proj
    cvt_kernel<<<n4_x / 256, 256>>>((const float4*)ao, (__nv_bfloat162*)aoh, (__nv_bfloat162*)aol, n4_x);
    mma_gemm_nt<<<dim3(D_DIM / 128, T_DIM / 128), 256, GEMM_SMEM>>>(
        aoh, aol, wph, wpl, out, b_proj, D_DIM, D_DIM);
}

// round 10
// speedup vs baseline: 1.6531x; 1.0349x over previous
#include <cuda_runtime.h>
#include <cuda_bf16.h>
#include <math.h>
#include <stdint.h>
#include <stddef.h>

#define T_DIM 2048
#define D_DIM 2048
#define H_DIM 16
#define C_DIM 128

// ---------------- scratch (device globals; no runtime allocation) ----------
__device__ __align__(128) float g_qkv[(size_t)T_DIM * 3 * D_DIM];
__device__ __align__(128) float g_ao [(size_t)T_DIM * D_DIM];
__device__ __align__(128) __nv_bfloat16 g_xh [(size_t)T_DIM * D_DIM];
__device__ __align__(128) __nv_bfloat16 g_xl [(size_t)T_DIM * D_DIM];
__device__ __align__(128) __nv_bfloat16 g_wah[(size_t)3 * D_DIM * D_DIM];
__device__ __align__(128) __nv_bfloat16 g_wal[(size_t)3 * D_DIM * D_DIM];
__device__ __align__(128) __nv_bfloat16 g_wph[(size_t)D_DIM * D_DIM];
__device__ __align__(128) __nv_bfloat16 g_wpl[(size_t)D_DIM * D_DIM];
__device__ __align__(128) __nv_bfloat16 g_aoh[(size_t)T_DIM * D_DIM];
__device__ __align__(128) __nv_bfloat16 g_aol[(size_t)T_DIM * D_DIM];
__device__ __align__(128) __nv_bfloat16 g_qh[(size_t)H_DIM * T_DIM * C_DIM];
__device__ __align__(128) __nv_bfloat16 g_ql[(size_t)H_DIM * T_DIM * C_DIM];
__device__ __align__(128) __nv_bfloat16 g_kh[(size_t)H_DIM * T_DIM * C_DIM];
__device__ __align__(128) __nv_bfloat16 g_kl[(size_t)H_DIM * T_DIM * C_DIM];
__device__ __align__(128) __nv_bfloat16 g_vh[(size_t)H_DIM * T_DIM * C_DIM];
__device__ __align__(128) __nv_bfloat16 g_vl[(size_t)H_DIM * T_DIM * C_DIM];

// ---------------- asm helpers ----------------------------------------------
__device__ __forceinline__ uint32_t smem_u32(const void* p) {
    return (uint32_t)__cvta_generic_to_shared(p);
}
__device__ __forceinline__ void cpa16(void* s, const void* g) {
    asm volatile("cp.async.cg.shared.global [%0], [%1], 16;\n"
                 :: "r"(smem_u32(s)), "l"(g));
}
__device__ __forceinline__ void cpa_commit() {
    asm volatile("cp.async.commit_group;\n");
}
__device__ __forceinline__ void ldm_x4(uint32_t& d0, uint32_t& d1,
                                       uint32_t& d2, uint32_t& d3,
                                       const void* p) {
    asm volatile("ldmatrix.sync.aligned.m8n8.x4.shared.b16 {%0,%1,%2,%3}, [%4];\n"
                 : "=r"(d0), "=r"(d1), "=r"(d2), "=r"(d3)
                 : "r"(smem_u32(p)));
}
__device__ __forceinline__ void ldm_x4_t(uint32_t& d0, uint32_t& d1,
                                         uint32_t& d2, uint32_t& d3,
                                         const void* p) {
    asm volatile("ldmatrix.sync.aligned.m8n8.x4.trans.shared.b16 {%0,%1,%2,%3}, [%4];\n"
                 : "=r"(d0), "=r"(d1), "=r"(d2), "=r"(d3)
                 : "r"(smem_u32(p)));
}
__device__ __forceinline__ void mma16816(float* c, const uint32_t* a,
                                         const uint32_t* b) {
    asm volatile("mma.sync.aligned.m16n8k16.row.col.f32.bf16.bf16.f32 "
                 "{%0,%1,%2,%3}, {%4,%5,%6,%7}, {%8,%9}, {%0,%1,%2,%3};\n"
                 : "+f"(c[0]), "+f"(c[1]), "+f"(c[2]), "+f"(c[3])
                 : "r"(a[0]), "r"(a[1]), "r"(a[2]), "r"(a[3]),
                   "r"(b[0]), "r"(b[1]));
}
__device__ __forceinline__ uint32_t pack_hi(float a, float b) {
    __nv_bfloat162 v = __float22bfloat162_rn(make_float2(a, b));
    return *(uint32_t*)&v;
}
__device__ __forceinline__ uint32_t pack_lo(float a, float b) {
    float ra = a - __bfloat162float(__float2bfloat16_rn(a));
    float rb = b - __bfloat162float(__float2bfloat16_rn(b));
    __nv_bfloat162 v = __float22bfloat162_rn(make_float2(ra, rb));
    return *(uint32_t*)&v;
}

// ---------------- fp32 -> bf16 (hi, lo) conversion --------------------------
__global__ __launch_bounds__(256)
void cvt_kernel(const float4* __restrict__ src,
                __nv_bfloat162* __restrict__ hi,
                __nv_bfloat162* __restrict__ lo, int n4)
{
    int i = blockIdx.x * 256 + threadIdx.x;
    if (i >= n4) return;
    float4 v = src[i];
    __nv_bfloat16 h0 = __float2bfloat16_rn(v.x);
    __nv_bfloat16 h1 = __float2bfloat16_rn(v.y);
    __nv_bfloat16 h2 = __float2bfloat16_rn(v.z);
    __nv_bfloat16 h3 = __float2bfloat16_rn(v.w);
    __nv_bfloat16 l0 = __float2bfloat16_rn(v.x - __bfloat162float(h0));
    __nv_bfloat16 l1 = __float2bfloat16_rn(v.y - __bfloat162float(h1));
    __nv_bfloat16 l2 = __float2bfloat16_rn(v.z - __bfloat162float(h2));
    __nv_bfloat16 l3 = __float2bfloat16_rn(v.w - __bfloat162float(h3));
    __nv_bfloat162 a; a.x = h0; a.y = h1;
    __nv_bfloat162 b; b.x = h2; b.y = h3;
    __nv_bfloat162 c; c.x = l0; c.y = l1;
    __nv_bfloat162 d; d.x = l2; d.y = l3;
    hi[2 * i] = a; hi[2 * i + 1] = b;
    lo[2 * i] = c; lo[2 * i + 1] = d;
}

// ---------------- bf16x3 NT GEMM (HMMA, merged passes) ----------------------
// C[m,n] = sum_k (Ah+Al)[m,k]*(Bh+Bl)[n,k] + bias[n]  (drop Al*Bl)
// Block 128x128, BK=32, 8 warps (2x4), warp tile 64x32.
// Per stage: Ah(8K) Al(8K) Bh(8K) Bl(8K). 3 stages, 1 sync/iter,
// fragments loaded ONCE per k-step and reused across the 3 passes.
#define GSTG 32768
#define GEMM_STAGES 3
#define GEMM_SMEM (GEMM_STAGES * GSTG)

__device__ __forceinline__ void gemm_iter(const char* s, float acc[4][4][4],
                                          int wm, int wn, int lane)
{
#pragma unroll
    for (int ks = 0; ks < 2; ks++) {
        const int ch = 2 * ks + (lane >> 4);
        // B fragments (hi+lo), loaded once
        uint32_t bh[4][2], bl[4][2];
#pragma unroll
        for (int ip = 0; ip < 2; ip++) {
            int r   = wn * 32 + ip * 16 + ((lane >> 3) & 1) * 8 + (lane & 7);
            int off = r * 64 + ((ch ^ ((r >> 1) & 3)) << 4);
            uint32_t r0, r1, r2, r3;
            ldm_x4(r0, r1, r2, r3, s + 16384 + off);
            bh[2 * ip][0] = r0; bh[2 * ip + 1][0] = r1;
            bh[2 * ip][1] = r2; bh[2 * ip + 1][1] = r3;
            ldm_x4(r0, r1, r2, r3, s + 24576 + off);
            bl[2 * ip][0] = r0; bl[2 * ip + 1][0] = r1;
            bl[2 * ip][1] = r2; bl[2 * ip + 1][1] = r3;
        }
        // A fragments per im (hi+lo), then all 12 MMAs for that im
#pragma unroll
        for (int im = 0; im < 4; im++) {
            int r   = wm * 64 + im * 16 + ((lane >> 3) & 1) * 8 + (lane & 7);
            int off = r * 64 + ((ch ^ ((r >> 1) & 3)) << 4);
            uint32_t ah[4], al[4];
            ldm_x4(ah[0], ah[1], ah[2], ah[3], s + off);
            ldm_x4(al[0], al[1], al[2], al[3], s + 8192 + off);
#pragma unroll
            for (int in = 0; in < 4; in++) mma16816(acc[im][in], ah, bh[in]);
#pragma unroll
            for (int in = 0; in < 4; in++) mma16816(acc[im][in], al, bh[in]);
#pragma unroll
            for (int in = 0; in < 4; in++) mma16816(acc[im][in], ah, bl[in]);
        }
    }
}

__global__ __launch_bounds__(256, 2)
void mma_gemm_nt(const __nv_bfloat16* __restrict__ Ah,
                 const __nv_bfloat16* __restrict__ Al,
                 const __nv_bfloat16* __restrict__ Bh,
                 const __nv_bfloat16* __restrict__ Bl,
                 float* __restrict__ C,
                 const float* __restrict__ bias,
                 int N, int K)
{
    extern __shared__ __align__(16) char smem_dyn[];

    const int tid  = threadIdx.x;
    const int wid  = tid >> 5, lane = tid & 31;
    const int wm   = wid >> 2, wn = wid & 3;
    const int m0   = blockIdx.y * 128, n0 = blockIdx.x * 128;

    const int c0_  = tid,        r0_ = c0_ >> 2, j0_ = c0_ & 3;
    const int c1_  = tid + 256,  r1_ = c1_ >> 2, j1_ = c1_ & 3;
    const int off0 = r0_ * 64 + ((j0_ ^ ((r0_ >> 1) & 3)) << 4);
    const int off1 = r1_ * 64 + ((j1_ ^ ((r1_ >> 1) & 3)) << 4);

    float acc[4][4][4];
#pragma unroll
    for (int a = 0; a < 4; a++)
#pragma unroll
        for (int b = 0; b < 4; b++)
#pragma unroll
            for (int c = 0; c < 4; c++) acc[a][b][c] = 0.f;

    const int niter = K / 32;

    auto load_stage = [&](char* s, int k0) {
        size_t ga0 = (size_t)(m0 + r0_) * K + k0 + j0_ * 8;
        size_t gb0 = (size_t)(n0 + r0_) * K + k0 + j0_ * 8;
        size_t ga1 = (size_t)(m0 + r1_) * K + k0 + j1_ * 8;
        size_t gb1 = (size_t)(n0 + r1_) * K + k0 + j1_ * 8;
        cpa16(s + off0,         Ah + ga0);
        cpa16(s + 8192 + off0,  Al + ga0);
        cpa16(s + 16384 + off0, Bh + gb0);
        cpa16(s + 24576 + off0, Bl + gb0);
        cpa16(s + off1,         Ah + ga1);
        cpa16(s + 8192 + off1,  Al + ga1);
        cpa16(s + 16384 + off1, Bh + gb1);
        cpa16(s + 24576 + off1, Bl + gb1);
    };

    // prologue: stages 0,1 in flight
    load_stage(smem_dyn, 0);           cpa_commit();
    load_stage(smem_dyn + GSTG, 32);   cpa_commit();

    for (int i = 0; i < niter; i++) {
        if (i + 1 < niter)
            asm volatile("cp.async.wait_group 1;\n");   // stage i done
        else
            asm volatile("cp.async.wait_group 0;\n");
        __syncthreads();   // stage i visible to all; all warps past compute(i-1)
        if (i + 2 < niter) {
            load_stage(smem_dyn + (size_t)((i + 2) % GEMM_STAGES) * GSTG,
                       (i + 2) * 32);
            cpa_commit();
        }
        gemm_iter(smem_dyn + (size_t)(i % GEMM_STAGES) * GSTG,
                  acc, wm, wn, lane);
    }

    // epilogue
#pragma unroll
    for (int im = 0; im < 4; im++) {
        int row = m0 + wm * 64 + im * 16 + (lane >> 2);
#pragma unroll
        for (int in = 0; in < 4; in++) {
            int col = n0 + wn * 32 + in * 8 + 2 * (lane & 3);
            float b0 = bias[col], b1 = bias[col + 1];
            float2 o0, o1;
            o0.x = acc[im][in][0] + b0; o0.y = acc[im][in][1] + b1;
            o1.x = acc[im][in][2] + b0; o1.y = acc[im][in][3] + b1;
            *(float2*)(C + (size_t)row * N + col)       = o0;
            *(float2*)(C + (size_t)(row + 8) * N + col) = o1;
        }
    }
}

// ---------------- LayerNorm + RoPE -> bf16 hi/lo Q(scaled), K, V ------------
__global__ __launch_bounds__(128)
void lnrope_kernel(const float* __restrict__ qkv,
                   const float* __restrict__ qw,
                   const float* __restrict__ kw,
                   __nv_bfloat16* __restrict__ Qh, __nv_bfloat16* __restrict__ Ql,
                   __nv_bfloat16* __restrict__ Kh, __nv_bfloat16* __restrict__ Kl,
                   __nv_bfloat16* __restrict__ Vh, __nv_bfloat16* __restrict__ Vl)
{
    const int t = blockIdx.x, h = blockIdx.y, c = threadIdx.x;
    const size_t base = (size_t)t * (3 * D_DIM) + (size_t)h * C_DIM + c;
    const float qv = qkv[base];
    const float kv = qkv[base + D_DIM];
    const float vv = qkv[base + 2 * D_DIM];

    __shared__ float red[4][4];
    float s0 = qv, s1 = qv * qv, s2 = kv, s3 = kv * kv;
#pragma unroll
    for (int o = 16; o; o >>= 1) {
        s0 += __shfl_xor_sync(0xffffffffu, s0, o);
        s1 += __shfl_xor_sync(0xffffffffu, s1, o);
        s2 += __shfl_xor_sync(0xffffffffu, s2, o);
        s3 += __shfl_xor_sync(0xffffffffu, s3, o);
    }
    const int w = c >> 5;
    if ((c & 31) == 0) { red[w][0] = s0; red[w][1] = s1; red[w][2] = s2; red[w][3] = s3; }
    __syncthreads();
    s0 = red[0][0] + red[1][0] + red[2][0] + red[3][0];
    s1 = red[0][1] + red[1][1] + red[2][1] + red[3][1];
    s2 = red[0][2] + red[1][2] + red[2][2] + red[3][2];
    s3 = red[0][3] + red[1][3] + red[2][3] + red[3][3];

    const float inv_n = 1.0f / (float)C_DIM;
    const float muq = s0 * inv_n, muk = s2 * inv_n;
    const float varq = s1 * inv_n - muq * muq;
    const float vark = s3 * inv_n - muk * muk;
    const float qn = (qv - muq) * rsqrtf(varq + 1e-6f) * qw[c];
    const float kn = (kv - muk) * rsqrtf(vark + 1e-6f) * kw[c];

    __shared__ float qs[C_DIM], ks[C_DIM];
    qs[c] = qn; ks[c] = kn;
    __syncthreads();

    const int i = c >> 1;
    const float inv_freq = powf(10000.f, -(float)(2 * i) / (float)C_DIM);
    float sn, cs;
    sincosf((float)t * inv_freq, &sn, &cs);
    const float qrot = (c & 1) ? qs[c - 1] : -qs[c + 1];
    const float krot = (c & 1) ? ks[c - 1] : -ks[c + 1];

    const float qsc = (qn * cs + qrot * sn) * 0.08838834764831845f;
    const float ksc = kn * cs + krot * sn;

    const size_t o = ((size_t)h * T_DIM + t) * C_DIM + c;
    __nv_bfloat16 b;
    b = __float2bfloat16_rn(qsc); Qh[o] = b;
    Ql[o] = __float2bfloat16_rn(qsc - __bfloat162float(b));
    b = __float2bfloat16_rn(ksc); Kh[o] = b;
    Kl[o] = __float2bfloat16_rn(ksc - __bfloat162float(b));
    b = __float2bfloat16_rn(vv);  Vh[o] = b;
    Vl[o] = __float2bfloat16_rn(vv - __bfloat162float(b));
}

// ---------------- tensor-core causal flash attention (HMMA) -----------------
#define FA_SMEM (6 * 32768)

__global__ __launch_bounds__(256, 1)
void fa_kernel(const __nv_bfloat16* __restrict__ Qhg,
               const __nv_bfloat16* __restrict__ Qlg,
               const __nv_bfloat16* __restrict__ Khg,
               const __nv_bfloat16* __restrict__ Klg,
               const __nv_bfloat16* __restrict__ Vhg,
               const __nv_bfloat16* __restrict__ Vlg,
               float* __restrict__ Og)
{
    extern __shared__ __align__(16) char fsm[];
    char* sQh = fsm;
    char* sQl = fsm + 32768;
    char* sKh = fsm + 65536;
    char* sKl = fsm + 98304;
    char* sVh = fsm + 131072;
    char* sVl = fsm + 163840;

    const int m0 = (gridDim.x - 1 - blockIdx.x) * 128;
    const int h  = blockIdx.y;
    const size_t hb = (size_t)h * T_DIM * C_DIM;

    const int tid  = threadIdx.x;
    const int w    = tid >> 5, lane = tid & 31;

#pragma unroll
    for (int i = 0; i < 8; i++) {
        int c = tid + i * 256;
        int row = c >> 4, ch = c & 15;
        int dst = row * 256 + ((ch ^ (row & 7)) << 4);
        size_t src = hb + (size_t)(m0 + row) * C_DIM + ch * 8;
        cpa16(sQh + dst, Qhg + src);
        cpa16(sQl + dst, Qlg + src);
    }
    cpa_commit();

    float O[16][4];
#pragma unroll
    for (int f = 0; f < 16; f++)
#pragma unroll
        for (int x = 0; x < 4; x++) O[f][x] = 0.f;
    float mrow0 = -1e30f, mrow1 = -1e30f, lrow0 = 0.f, lrow1 = 0.f;

    const int arow = w * 16 + ((lane >> 3) & 1) * 8 + (lane & 7);
    const int achb = lane >> 4;

    for (int kt = 0; kt <= m0; kt += 128) {
        __syncthreads();
#pragma unroll
        for (int i = 0; i < 8; i++) {
            int c = tid + i * 256;
            int row = c >> 4, ch = c & 15;
            int dst = row * 256 + ((ch ^ (row & 7)) << 4);
            size_t src = hb + (size_t)(kt + row) * C_DIM + ch * 8;
            cpa16(sKh + dst, Khg + src);
            cpa16(sKl + dst, Klg + src);
            cpa16(sVh + dst, Vhg + src);
            cpa16(sVl + dst, Vlg + src);
        }
        cpa_commit();
        asm volatile("cp.async.wait_group 0;\n");
        __syncthreads();

        float S[16][4];
#pragma unroll
        for (int f = 0; f < 16; f++)
#pragma unroll
            for (int x = 0; x < 4; x++) S[f][x] = 0.f;

#pragma unroll
        for (int ks = 0; ks < 8; ks++) {
            const int ch = 2 * ks + achb;
            uint32_t aQh[4], aQl[4];
            ldm_x4(aQh[0], aQh[1], aQh[2], aQh[3],
                   sQh + arow * 256 + ((ch ^ (arow & 7)) << 4));
            ldm_x4(aQl[0], aQl[1], aQl[2], aQl[3],
                   sQl + arow * 256 + ((ch ^ (arow & 7)) << 4));
#pragma unroll
            for (int nb = 0; nb < 8; nb++) {
                const int brow = nb * 16 + ((lane >> 3) & 1) * 8 + (lane & 7);
                const int boff = brow * 256 + ((ch ^ (brow & 7)) << 4);
                uint32_t r0, r1, r2, r3;
                ldm_x4(r0, r1, r2, r3, sKh + boff);
                uint32_t blo[2] = {r0, r2}, bhi[2] = {r1, r3};
                mma16816(S[2 * nb],     aQh, blo);
                mma16816(S[2 * nb + 1], aQh, bhi);
                mma16816(S[2 * nb],     aQl, blo);
                mma16816(S[2 * nb + 1], aQl, bhi);
                ldm_x4(r0, r1, r2, r3, sKl + boff);
                uint32_t clo[2] = {r0, r2}, chi[2] = {r1, r3};
                mma16816(S[2 * nb],     aQh, clo);
                mma16816(S[2 * nb + 1], aQh, chi);
            }
        }

        const int row0 = m0 + w * 16 + (lane >> 2);
        if (kt == m0) {
#pragma unroll
            for (int f = 0; f < 16; f++) {
                const int col = kt + f * 8 + 2 * (lane & 3);
                if (col     > row0)     S[f][0] = -1e30f;
                if (col + 1 > row0)     S[f][1] = -1e30f;
                if (col     > row0 + 8) S[f][2] = -1e30f;
                if (col + 1 > row0 + 8) S[f][3] = -1e30f;
            }
        }

        float mx0 = -1e30f, mx1 = -1e30f;
#pragma unroll
        for (int f = 0; f < 16; f++) {
            mx0 = fmaxf(mx0, fmaxf(S[f][0], S[f][1]));
            mx1 = fmaxf(mx1, fmaxf(S[f][2], S[f][3]));
        }
        mx0 = fmaxf(mx0, __shfl_xor_sync(0xffffffffu, mx0, 1));
        mx0 = fmaxf(mx0, __shfl_xor_sync(0xffffffffu, mx0, 2));
        mx1 = fmaxf(mx1, __shfl_xor_sync(0xffffffffu, mx1, 1));
        mx1 = fmaxf(mx1, __shfl_xor_sync(0xffffffffu, mx1, 2));

        const float nm0 = fmaxf(mrow0, mx0);
        const float nm1 = fmaxf(mrow1, mx1);
        const float al0 = __expf(mrow0 - nm0);
        const float al1 = __expf(mrow1 - nm1);
        mrow0 = nm0; mrow1 = nm1;

        float sum0 = 0.f, sum1 = 0.f;
#pragma unroll
        for (int f = 0; f < 16; f++) {
            S[f][0] = __expf(S[f][0] - nm0);
            S[f][1] = __expf(S[f][1] - nm0);
            S[f][2] = __expf(S[f][2] - nm1);
            S[f][3] = __expf(S[f][3] - nm1);
            sum0 += S[f][0] + S[f][1];
            sum1 += S[f][2] + S[f][3];
        }
        sum0 += __shfl_xor_sync(0xffffffffu, sum0, 1);
        sum0 += __shfl_xor_sync(0xffffffffu, sum0, 2);
        sum1 += __shfl_xor_sync(0xffffffffu, sum1, 1);
        sum1 += __shfl_xor_sync(0xffffffffu, sum1, 2);
        lrow0 = lrow0 * al0 + sum0;
        lrow1 = lrow1 * al1 + sum1;

#pragma unroll
        for (int f = 0; f < 16; f++) {
            O[f][0] *= al0; O[f][1] *= al0;
            O[f][2] *= al1; O[f][3] *= al1;
        }

#pragma unroll
        for (int kb = 0; kb < 8; kb++) {
            uint32_t aPh[4], aPl[4];
            aPh[0] = pack_hi(S[2 * kb][0],     S[2 * kb][1]);
            aPh[1] = pack_hi(S[2 * kb][2],     S[2 * kb][3]);
            aPh[2] = pack_hi(S[2 * kb + 1][0], S[2 * kb + 1][1]);
            aPh[3] = pack_hi(S[2 * kb + 1][2], S[2 * kb + 1][3]);
            aPl[0] = pack_lo(S[2 * kb][0],     S[2 * kb][1]);
            aPl[1] = pack_lo(S[2 * kb][2],     S[2 * kb][3]);
            aPl[2] = pack_lo(S[2 * kb + 1][0], S[2 * kb + 1][1]);
            aPl[3] = pack_lo(S[2 * kb + 1][2], S[2 * kb + 1][3]);

            const int kvrow = kb * 16 + ((lane >> 3) & 1) * 8 + (lane & 7);
#pragma unroll
            for (int nb = 0; nb < 8; nb++) {
                const int chv  = 2 * nb + (lane >> 4);
                const int voff = kvrow * 256 + ((chv ^ (kvrow & 7)) << 4);
                uint32_t r0, r1, r2, r3;
                ldm_x4_t(r0, r1, r2, r3, sVh + voff);
                uint32_t blo[2] = {r0, r1}, bhi[2] = {r2, r3};
                mma16816(O[2 * nb],     aPh, blo);
                mma16816(O[2 * nb + 1], aPh, bhi);
                mma16816(O[2 * nb],     aPl, blo);
                mma16816(O[2 * nb + 1], aPl, bhi);
                ldm_x4_t(r0, r1, r2, r3, sVl + voff);
                uint32_t clo[2] = {r0, r1}, chi[2] = {r2, r3};
                mma16816(O[2 * nb],     aPh, clo);
                mma16816(O[2 * nb + 1], aPh, chi);
            }
        }
    }

    const float inv0 = 1.f / lrow0;
    const float inv1 = 1.f / lrow1;
    const int orow = m0 + w * 16 + (lane >> 2);
#pragma unroll
    for (int f = 0; f < 16; f++) {
        const int col = h * C_DIM + f * 8 + 2 * (lane & 3);
        float2 o0, o1;
        o0.x = O[f][0] * inv0; o0.y = O[f][1] * inv0;
        o1.x = O[f][2] * inv1; o1.y = O[f][3] * inv1;
        *(float2*)(Og + (size_t)orow * D_DIM + col)       = o0;
        *(float2*)(Og + (size_t)(orow + 8) * D_DIM + col) = o1;
    }
}

// ---------------------------------------------------------------------------
extern "C" void kernel_launch(void* const* d_in, const int* in_sizes, int n_in,
                              void* d_out, int out_size)
{
    const float* x      = (const float*)d_in[0];
    const float* W_attn = (const float*)d_in[1];
    const float* b_attn = (const float*)d_in[2];
    const float* W_proj = (const float*)d_in[3];
    const float* b_proj = (const float*)d_in[4];
    const float* q_ln_w = (const float*)d_in[5];
    const float* k_ln_w = (const float*)d_in[6];
    float* out = (float*)d_out;

    float *qkv, *ao;
    __nv_bfloat16 *xh, *xl, *wah, *wal, *wph, *wpl, *aoh, *aol;
    __nv_bfloat16 *qh, *ql, *kh, *kl, *vh, *vl;
    cudaGetSymbolAddress((void**)&qkv, g_qkv);
    cudaGetSymbolAddress((void**)&ao,  g_ao);
    cudaGetSymbolAddress((void**)&xh,  g_xh);
    cudaGetSymbolAddress((void**)&xl,  g_xl);
    cudaGetSymbolAddress((void**)&wah, g_wah);
    cudaGetSymbolAddress((void**)&wal, g_wal);
    cudaGetSymbolAddress((void**)&wph, g_wph);
    cudaGetSymbolAddress((void**)&wpl, g_wpl);
    cudaGetSymbolAddress((void**)&aoh, g_aoh);
    cudaGetSymbolAddress((void**)&aol, g_aol);
    cudaGetSymbolAddress((void**)&qh,  g_qh);
    cudaGetSymbolAddress((void**)&ql,  g_ql);
    cudaGetSymbolAddress((void**)&kh,  g_kh);
    cudaGetSymbolAddress((void**)&kl,  g_kl);
    cudaGetSymbolAddress((void**)&vh,  g_vh);
    cudaGetSymbolAddress((void**)&vl,  g_vl);

    cudaFuncSetAttribute(mma_gemm_nt,
                         cudaFuncAttributeMaxDynamicSharedMemorySize, GEMM_SMEM);
    cudaFuncSetAttribute(fa_kernel,
                         cudaFuncAttributeMaxDynamicSharedMemorySize, FA_SMEM);

    const int n4_x  = T_DIM * D_DIM / 4;
    const int n4_wa = 3 * D_DIM * D_DIM / 4;
    const int n4_wp = D_DIM * D_DIM / 4;

    // 0) split fp32 -> bf16 hi/lo
    cvt_kernel<<<n4_x  / 256, 256>>>((const float4*)x,      (__nv_bfloat162*)xh,  (__nv_bfloat162*)xl,  n4_x);
    cvt_kernel<<<n4_wa / 256, 256>>>((const float4*)W_attn, (__nv_bfloat162*)wah, (__nv_bfloat162*)wal, n4_wa);
    cvt_kernel<<<n4_wp / 256, 256>>>((const float4*)W_proj, (__nv_bfloat162*)wph, (__nv_bfloat162*)wpl, n4_wp);

    // 1) QKV = x @ W_attn^T + b_attn   (HMMA bf16x3)
    mma_gemm_nt<<<dim3(3 * D_DIM / 128, T_DIM / 128), 256, GEMM_SMEM>>>(
        xh, xl, wah, wal, qkv, b_attn, 3 * D_DIM, D_DIM);

    // 2) LayerNorm + RoPE -> bf16 hi/lo Q(scaled), K, V in [H,T,C]
    lnrope_kernel<<<dim3(T_DIM, H_DIM), 128>>>(qkv, q_ln_w, k_ln_w,
                                               qh, ql, kh, kl, vh, vl);

    // 3) tensor-core causal flash attention -> ao [T, D]
    fa_kernel<<<dim3(T_DIM / 128, H_DIM), 256, FA_SMEM>>>(
        qh, ql, kh, kl, vh, vl, ao);

    // 4) split ao, then out = ao @ W_proj^T + b_proj
    cvt_kernel<<<n4_x / 256, 256>>>((const float4*)ao, (__nv_bfloat162*)aoh, (__nv_bfloat162*)aol, n4_x);
    mma_gemm_nt<<<dim3(D_DIM / 128, T_DIM / 128), 256, GEMM_SMEM>>>(
        aoh, aol, wph, wpl, out, b_proj, D_DIM, D_DIM);
}